// round 6
// baseline (speedup 1.0000x reference)
#include <cuda_runtime.h>
#include <math.h>

#define BB 8
#define NN 2048
#define BN (BB*NN)
#define KK 30
#define CAP 288          // candidate buffer capacity

// ---- output layout (float32, tuple arrays concatenated, flattened C-order) ----
#define NS_OFF 0                         // node_scalar (8,2048,7)      = 114688
#define NV_OFF 114688                    // node_vector (8,2048,3,3)    = 147456
#define DN_OFF 262144                    // D_neighbors (8,2048,30)     = 491520
#define EI_OFF 753664                    // E_idx       (8,2048,30)     = 491520
#define CM_OFF 1245184                   // cm_nb       (8,2048,30)     = 491520
#define RM_OFF 1736704                   // rm_nb       (8,2048,30)     = 491520

// ---- scratch (__device__ globals: no allocation allowed) ----
// w lane packs: (res_idx << 2) | (rm << 1) | cm   (as int bits)
__device__ float4 g_xca[BN];

__device__ __forceinline__ bool read_mask(const void* p, int i, int fmt) {
    if (fmt == 2) return ((const float*)p)[i] != 0.0f;
    if (fmt == 1) return ((const int*)p)[i]   != 0;
    return ((const unsigned char*)p)[i] != 0;
}

// ---------------------------------------------------------------------------
// Pack CA coords + (res_idx, rm, cm) into one float4 per residue.
// Each block independently detects the bool serialization format from the
// first 4 KB of coord_mask (coord_mask ~90% true):
//  uint8  : nonzero bytes at off-word offsets, none == 0x3F at r==3
//  int32  : only bytes at offset%4==0 nonzero
//  float32: 1.0f = [00,00,80,3F] -> byte 0x3F at r==3
// ---------------------------------------------------------------------------
__global__ void pack_kernel(const float* __restrict__ coords,
                            const void* __restrict__ cm,
                            const int*  __restrict__ res_idx,
                            const void* __restrict__ pm) {
    __shared__ int s3F, sOff;
    int tid = threadIdx.x;
    if (tid == 0) { s3F = 0; sOff = 0; }
    __syncthreads();
    {
        const unsigned char* c = (const unsigned char*)cm;
        int offF = 0, f3F = 0;
        #pragma unroll
        for (int t = 0; t < 16; t++) {
            int i = tid * 16 + t;
            unsigned char v = c[i];
            int r = i & 3;
            if (r != 0 && v != 0) { offF = 1; if (r == 3 && v == 0x3F) f3F = 1; }
        }
        if (offF) atomicOr(&sOff, 1);
        if (f3F)  atomicOr(&s3F, 1);
    }
    __syncthreads();
    int fmt = s3F ? 2 : (sOff ? 0 : 1);

    int idx = blockIdx.x * blockDim.x + tid;
    if (idx >= BN) return;
    int w = (res_idx[idx] << 2)
          | (read_mask(pm, idx, fmt) ? 0 : 2)       // rm = ~padding
          | (read_mask(cm, idx, fmt) ? 1 : 0);
    float4 v;
    v.x = coords[idx * 9 + 3];
    v.y = coords[idx * 9 + 4];
    v.z = coords[idx * 9 + 5];
    v.w = __int_as_float(w);
    g_xca[idx] = v;
}

// ---- small vec helpers (match jax: v / sqrt(dot(v,v) + 1e-8)) ----
__device__ __forceinline__ void nrm3(float& x, float& y, float& z) {
    float inv = 1.0f / sqrtf(x*x + y*y + z*z + 1e-8f);
    x *= inv; y *= inv; z *= inv;
}
__device__ __forceinline__ void cross3(float ax, float ay, float az,
                                       float bx, float by, float bz,
                                       float& cx, float& cy, float& cz) {
    cx = ay*bz - az*by;
    cy = az*bx - ax*bz;
    cz = ax*by - ay*bx;
}

// ---------------------------------------------------------------------------
// node_scalar (dihedrals + mask) and node_vector (fwd, bwd, sidechain)
// ---------------------------------------------------------------------------
__global__ void features_kernel(const float* __restrict__ coords,
                                float* __restrict__ out) {
    int idx = blockIdx.x * blockDim.x + threadIdx.x;
    if (idx >= BN) return;
    int b = idx >> 11, n = idx & (NN - 1);
    const float* Xf = coords + (size_t)b * NN * 9;   // (3N, 3) flat view

    float cosv[3], sinv[3];
    #pragma unroll
    for (int t = 0; t < 3; t++) {
        int f = 3 * n + t;
        if (f < 1 || f >= 3 * NN - 2) { cosv[t] = 1.0f; sinv[t] = 0.0f; continue; }
        const float* p0 = Xf + (size_t)(f - 1) * 3;
        const float* p1 = Xf + (size_t)(f    ) * 3;
        const float* p2 = Xf + (size_t)(f + 1) * 3;
        const float* p3 = Xf + (size_t)(f + 2) * 3;
        float u2x = p1[0]-p0[0], u2y = p1[1]-p0[1], u2z = p1[2]-p0[2];
        float u1x = p2[0]-p1[0], u1y = p2[1]-p1[1], u1z = p2[2]-p1[2];
        float u0x = p3[0]-p2[0], u0y = p3[1]-p2[1], u0z = p3[2]-p2[2];
        nrm3(u2x,u2y,u2z); nrm3(u1x,u1y,u1z); nrm3(u0x,u0y,u0z);
        float n2x,n2y,n2z, n1x,n1y,n1z;
        cross3(u2x,u2y,u2z, u1x,u1y,u1z, n2x,n2y,n2z); nrm3(n2x,n2y,n2z);
        cross3(u1x,u1y,u1z, u0x,u0y,u0z, n1x,n1y,n1z); nrm3(n1x,n1y,n1z);
        float cD = n2x*n1x + n2y*n1y + n2z*n1z;
        cD = fminf(fmaxf(cD, -1.0f + 1e-7f), 1.0f - 1e-7f);
        float sg = u2x*n1x + u2y*n1y + u2z*n1z;
        float s  = (sg > 0.0f) ? 1.0f : ((sg < 0.0f) ? -1.0f : 0.0f);
        float D  = s * acosf(cD);
        cosv[t] = cosf(D);
        sinv[t] = sinf(D);
    }

    float4 xc = g_xca[idx];
    float* ns = out + NS_OFF + (size_t)idx * 7;
    ns[0] = cosv[0]; ns[1] = cosv[1]; ns[2] = cosv[2];
    ns[3] = sinv[0]; ns[4] = sinv[1]; ns[5] = sinv[2];
    ns[6] = (__float_as_int(xc.w) & 1) ? 1.0f : 0.0f;

    float fx = 0.f, fy = 0.f, fz = 0.f, bx = 0.f, by = 0.f, bz = 0.f;
    if (n < NN - 1) {
        float4 xn = g_xca[idx + 1];
        fx = xn.x - xc.x; fy = xn.y - xc.y; fz = xn.z - xc.z;
        nrm3(fx, fy, fz);
    }
    if (n > 0) {
        float4 xp = g_xca[idx - 1];
        bx = xp.x - xc.x; by = xp.y - xc.y; bz = xp.z - xc.z;
        nrm3(bx, by, bz);
    }

    const float* at = coords + (size_t)idx * 9;
    float ox = at[3], oy = at[4], oz = at[5];
    float nx = at[0]-ox, ny = at[1]-oy, nz = at[2]-oz;
    float cx = at[6]-ox, cy = at[7]-oy, cz = at[8]-oz;
    nrm3(cx,cy,cz); nrm3(nx,ny,nz);
    float bix = cx+nx, biy = cy+ny, biz = cz+nz; nrm3(bix,biy,biz);
    float px,py,pz; cross3(cx,cy,cz, nx,ny,nz, px,py,pz); nrm3(px,py,pz);
    const float S13 = 0.5773502691896258f;   // sqrt(1/3)
    const float S23 = 0.8164965809277260f;   // sqrt(2/3)
    float sx = -bix*S13 - px*S23;
    float sy = -biy*S13 - py*S23;
    float sz = -biz*S13 - pz*S23;

    float* nv = out + NV_OFF + (size_t)idx * 9;
    nv[0]=fx; nv[1]=fy; nv[2]=fz;
    nv[3]=bx; nv[4]=by; nv[5]=bz;
    nv[6]=sx; nv[7]=sy; nv[8]=sz;
}

// ---------------------------------------------------------------------------
// Top-k via exact radix-select in the SQUARED-distance domain.
// dadj2 = cm2 ? (cov ? 0 : s) : penalty,  s = dx^2+dy^2+dz^2+1e-8 (no sqrt).
// sqrt is IEEE-monotone and penalties (>=1e8) dwarf real s (<=~3e4), so a
// dadj2-threshold candidate set is downward-closed under the true dadj
// order. Exact dadj keys (sqrtf on candidates only) feed the O(C^2) rank,
// which reproduces jax.lax.top_k (ascending value, ties by lowest index).
// Histogram digit = bits[30:20] of dadj2 (sign bit always 0): 2048 bins,
// bank-rotated bin -> ((bin&7)<<8)|(bin>>3) for a conflict-free scan.
// Refinement levels shift 20 -> 9 -> 0; fallback min-extraction is
// unreachable for this data but kept for safety.
// ---------------------------------------------------------------------------
__device__ __forceinline__ unsigned long long umin64(unsigned long long a,
                                                     unsigned long long b) {
    return a < b ? a : b;
}

__device__ __forceinline__ void emit(int row, int base, float4 xi, bool cmi,
                                     int rank, int j,
                                     float* __restrict__ out) {
    float4 xj = g_xca[base + j];
    float dx = xj.x - xi.x, dy = xj.y - xi.y, dz = xj.z - xi.z;
    float d  = sqrtf(dx*dx + dy*dy + dz*dz + 1e-8f);
    float D  = (cmi && (__float_as_int(xj.w) & 1)) ? d : 0.0f;
    size_t o = (size_t)row * KK + rank;
    out[DN_OFF + o] = D;
    out[EI_OFF + o] = (float)j;
    out[CM_OFF + o] = (D < 50000000.0f)   ? 1.0f : 0.0f;
    out[RM_OFF + o] = (D < 5000000000.0f) ? 1.0f : 0.0f;
}

__global__ void __launch_bounds__(256) topk_kernel(float* __restrict__ out) {
    __shared__ unsigned int       hist[2048];    // 8 KB, bank-rotated layout
    __shared__ unsigned long long cand[CAP];     // 2.25 KB
    __shared__ unsigned int       wtot[8];
    __shared__ unsigned long long s_win;
    __shared__ int s_cnt, s_piv, s_sb, s_excl, s_histpiv;

    int row = blockIdx.x;           // b*2048 + i
    int b   = row >> 11;
    int i   = row & (NN - 1);
    int tid = threadIdx.x;
    int lane = tid & 31, wid = tid >> 5;
    int base = b << 11;

    float4 xi = g_xca[row];
    int  wi  = __float_as_int(xi.w);
    int  ri  = wi >> 2;
    bool rmi = (wi & 2) != 0;
    bool cmi = (wi & 1) != 0;

    // ---- phase 1: D_adjust^2 bits for 8 j's, kept in registers (no sqrt) ----
    unsigned bj[8];
    #pragma unroll
    for (int q = 0; q < 8; q++) {
        int j = tid + q * 256;
        float4 xj = g_xca[base + j];
        float dx = xj.x - xi.x, dy = xj.y - xi.y, dz = xj.z - xi.z;
        float s  = dx*dx + dy*dy + dz*dz + 1e-8f;
        int  wj  = __float_as_int(xj.w);
        bool cm2 = cmi && (wj & 1);
        int  dr  = ri - (wj >> 2); if (dr < 0) dr = -dr;
        float dadj = (cm2 && dr > 3) ? s : 0.0f;
        if (!cm2) {
            int ds = i - j; if (ds < 0) ds = -ds;
            dadj += 100000000.0f + (float)ds * 1000000.0f;
        }
        if (!(rmi && (wj & 2))) dadj += 10000000000.0f;
        bj[q] = __float_as_uint(dadj);
    }

    // ---- radix refinement over dadj2 bits [30:20] (runs once normally) ----
    unsigned fmask = 0, prefix = 0;
    int shift = 20;
    int kbelow = 0;
    bool fellback = false;

    for (;;) {
        ((uint4*)hist)[tid]       = make_uint4(0u, 0u, 0u, 0u);
        ((uint4*)hist)[tid + 256] = make_uint4(0u, 0u, 0u, 0u);
        if (tid == 0) s_cnt = 0;
        __syncthreads();

        #pragma unroll
        for (int q = 0; q < 8; q++) {
            unsigned bq = bj[q];
            if ((bq & fmask) == prefix) {
                unsigned d = (bq >> shift) & 2047u;
                atomicAdd(&hist[((d & 7u) << 8) | (d >> 3)], 1u);
            }
        }
        __syncthreads();

        // superbin sums: thread tid covers original bins [tid*8, tid*8+8)
        unsigned v = 0;
        #pragma unroll
        for (int q = 0; q < 8; q++) v += hist[(q << 8) | tid];
        unsigned sc = v;
        #pragma unroll
        for (int o = 1; o < 32; o <<= 1) {
            unsigned n = __shfl_up_sync(0xffffffffu, sc, o);
            if (lane >= o) sc += n;
        }
        if (lane == 31) wtot[wid] = sc;
        __syncthreads();
        if (wid == 0) {
            unsigned w = (lane < 8) ? wtot[lane] : 0;
            #pragma unroll
            for (int o = 1; o < 8; o <<= 1) {
                unsigned n = __shfl_up_sync(0xffffffffu, w, o);
                if (lane >= o) w += n;
            }
            if (lane < 8) wtot[lane] = w;
        }
        __syncthreads();

        int kneed = KK - kbelow;
        unsigned incl = sc + (wid ? wtot[wid - 1] : 0);
        unsigned excl = incl - v;
        if ((int)incl >= kneed && (int)excl < kneed) { s_sb = tid; s_excl = (int)excl; }
        __syncthreads();
        if (tid == 0) {
            int sb = s_sb;
            unsigned cum = (unsigned)s_excl;
            int pd = sb * 8 + 7; unsigned hp = hist[(7u << 8) | sb];
            #pragma unroll
            for (int q = 0; q < 8; q++) {
                unsigned h = hist[(q << 8) | sb];
                if (cum + h >= (unsigned)kneed) { pd = sb * 8 + q; hp = h; break; }
                cum += h;
            }
            s_piv = pd; s_excl = (int)cum; s_histpiv = (int)hp;
        }
        __syncthreads();

        int below_total = kbelow + s_excl;           // strictly below pivot prefix
        unsigned nfmask  = fmask | (2047u << shift);
        unsigned nprefix = prefix | ((unsigned)s_piv << shift);

        if (below_total + s_histpiv <= CAP) {
            // compact: store EXACT dadj key ((sqrt bits)<<32 | j) for candidates
            #pragma unroll
            for (int q = 0; q < 8; q++) {
                unsigned bq = bj[q];
                if ((bq & nfmask) <= nprefix) {
                    int pos = atomicAdd(&s_cnt, 1);
                    if (pos < CAP) {
                        float f = __uint_as_float(bq);
                        unsigned be = (f < 1e8f) ? __float_as_uint(sqrtf(f)) : bq;
                        cand[pos] = ((unsigned long long)be << 32)
                                  | (unsigned)(tid + q * 256);
                    }
                }
            }
            __syncthreads();
            break;
        }
        if (shift == 0) { fellback = true; break; }
        fmask = nfmask; prefix = nprefix;
        shift = (shift == 20) ? 9 : 0;
        kbelow = below_total;
        __syncthreads();
    }

    if (!fellback) {
        int C = s_cnt; if (C > CAP) C = CAP;
        if (C <= 128) {
            // 2 threads per candidate: each scans half, combine via shfl
            int c0 = tid >> 1, half = tid & 1;
            unsigned long long k = (c0 < C) ? cand[c0] : ~0ULL;
            int rank = 0;
            for (int c = half; c < C; c += 2) rank += (cand[c] < k);
            rank += __shfl_xor_sync(0xffffffffu, rank, 1);
            if (c0 < C && half == 0 && rank < KK)
                emit(row, base, xi, cmi, rank, (int)(unsigned)(k & 0xffffffffu), out);
        } else {
            for (int t = tid; t < C; t += 256) {
                unsigned long long k = cand[t];
                int rank = 0;
                for (int c = 0; c < C; c++) rank += (cand[c] < k);
                if (rank < KK)
                    emit(row, base, xi, cmi, rank, (int)(unsigned)(k & 0xffffffffu), out);
            }
        }
    } else {
        // ---- fallback: exact iterative min-extraction on exact keys ----
        unsigned taken = 0;
        for (int s = 0; s < KK; s++) {
            unsigned long long local = ~0ULL;
            #pragma unroll
            for (int q = 0; q < 8; q++) {
                float f = __uint_as_float(bj[q]);
                unsigned be = (f < 1e8f) ? __float_as_uint(sqrtf(f)) : bj[q];
                unsigned long long k = ((unsigned long long)be << 32)
                                     | (unsigned)(tid + q * 256);
                if (!(taken & (1u << q))) local = umin64(local, k);
            }
            #pragma unroll
            for (int o = 16; o > 0; o >>= 1)
                local = umin64(local, __shfl_down_sync(0xffffffffu, local, o));
            if (lane == 0) ((unsigned long long*)hist)[wid] = local;
            __syncthreads();
            if (tid == 0) {
                unsigned long long m = ((unsigned long long*)hist)[0];
                #pragma unroll
                for (int w = 1; w < 8; w++)
                    m = umin64(m, ((unsigned long long*)hist)[w]);
                s_win = m;
                emit(row, base, xi, cmi, s, (int)(unsigned)(m & 0xffffffffu), out);
            }
            __syncthreads();
            unsigned long long m = s_win;
            int j = (int)(unsigned)(m & 0xffffffffu);
            if ((j & 255) == tid) taken |= 1u << (j >> 8);
            __syncthreads();
        }
    }
}

extern "C" void kernel_launch(void* const* d_in, const int* in_sizes, int n_in,
                              void* d_out, int out_size) {
    const float* coords = (const float*)d_in[0];
    const void*  cm     = d_in[1];
    const int*   ridx   = (const int*)d_in[2];
    const void*  pm     = d_in[3];
    float* out = (float*)d_out;

    pack_kernel<<<(BN + 255) / 256, 256>>>(coords, cm, ridx, pm);
    features_kernel<<<(BN + 255) / 256, 256>>>(coords, out);
    topk_kernel<<<BN, 256>>>(out);
}

// round 7
// speedup vs baseline: 1.1505x; 1.1505x over previous
#include <cuda_runtime.h>
#include <math.h>

#define BB 8
#define NN 2048
#define BN (BB*NN)
#define KK 30
#define CAP 288          // candidate buffer capacity per row

// ---- output layout (float32, tuple arrays concatenated, flattened C-order) ----
#define NS_OFF 0                         // node_scalar (8,2048,7)      = 114688
#define NV_OFF 114688                    // node_vector (8,2048,3,3)    = 147456
#define DN_OFF 262144                    // D_neighbors (8,2048,30)     = 491520
#define EI_OFF 753664                    // E_idx       (8,2048,30)     = 491520
#define CM_OFF 1245184                   // cm_nb       (8,2048,30)     = 491520
#define RM_OFF 1736704                   // rm_nb       (8,2048,30)     = 491520

// ---- scratch (__device__ globals: no allocation allowed) ----
// w lane packs: (res_idx << 2) | (rm << 1) | cm   (as int bits)
__device__ float4 g_xca[BN];

__device__ __forceinline__ bool read_mask(const void* p, int i, int fmt) {
    if (fmt == 2) return ((const float*)p)[i] != 0.0f;
    if (fmt == 1) return ((const int*)p)[i]   != 0;
    return ((const unsigned char*)p)[i] != 0;
}

// ---------------------------------------------------------------------------
// Pack CA coords + (res_idx, rm, cm) into one float4 per residue.
// Bool-format detection from the first 4 KB of coord_mask, read as uint4
// (coalesced). coord_mask ~90% true:
//  float32: 1.0f = [00,00,80,3F] -> some word has byte3 == 0x3F
//  uint8  : nonzero bytes at off-word positions, no 0x3F at byte3
//  int32  : only byte0 of each word nonzero
// ---------------------------------------------------------------------------
__global__ void pack_kernel(const float* __restrict__ coords,
                            const void* __restrict__ cm,
                            const int*  __restrict__ res_idx,
                            const void* __restrict__ pm) {
    __shared__ int s3F, sOff;
    int tid = threadIdx.x;
    if (tid == 0) { s3F = 0; sOff = 0; }
    __syncthreads();
    {
        uint4 v = ((const uint4*)cm)[tid];
        unsigned w[4] = {v.x, v.y, v.z, v.w};
        int offF = 0, f3F = 0;
        #pragma unroll
        for (int t = 0; t < 4; t++) {
            if (w[t] & 0xFFFFFF00u) offF = 1;
            if ((w[t] >> 24) == 0x3Fu) f3F = 1;
        }
        if (offF) atomicOr(&sOff, 1);
        if (f3F)  atomicOr(&s3F, 1);
    }
    __syncthreads();
    int fmt = s3F ? 2 : (sOff ? 0 : 1);

    int idx = blockIdx.x * blockDim.x + tid;
    if (idx >= BN) return;
    int w = (res_idx[idx] << 2)
          | (read_mask(pm, idx, fmt) ? 0 : 2)       // rm = ~padding
          | (read_mask(cm, idx, fmt) ? 1 : 0);
    float4 v;
    v.x = coords[idx * 9 + 3];
    v.y = coords[idx * 9 + 4];
    v.z = coords[idx * 9 + 5];
    v.w = __int_as_float(w);
    g_xca[idx] = v;
}

// ---- small vec helpers (match jax: v / sqrt(dot(v,v) + 1e-8)) ----
__device__ __forceinline__ void nrm3(float& x, float& y, float& z) {
    float inv = 1.0f / sqrtf(x*x + y*y + z*z + 1e-8f);
    x *= inv; y *= inv; z *= inv;
}
__device__ __forceinline__ void cross3(float ax, float ay, float az,
                                       float bx, float by, float bz,
                                       float& cx, float& cy, float& cz) {
    cx = ay*bz - az*by;
    cy = az*bx - ax*bz;
    cz = ax*by - ay*bx;
}

// ---------------------------------------------------------------------------
// node_scalar (dihedrals + mask) and node_vector (fwd, bwd, sidechain)
// ---------------------------------------------------------------------------
__global__ void features_kernel(const float* __restrict__ coords,
                                float* __restrict__ out) {
    int idx = blockIdx.x * blockDim.x + threadIdx.x;
    if (idx >= BN) return;
    int b = idx >> 11, n = idx & (NN - 1);
    const float* Xf = coords + (size_t)b * NN * 9;   // (3N, 3) flat view

    float cosv[3], sinv[3];
    #pragma unroll
    for (int t = 0; t < 3; t++) {
        int f = 3 * n + t;
        if (f < 1 || f >= 3 * NN - 2) { cosv[t] = 1.0f; sinv[t] = 0.0f; continue; }
        const float* p0 = Xf + (size_t)(f - 1) * 3;
        const float* p1 = Xf + (size_t)(f    ) * 3;
        const float* p2 = Xf + (size_t)(f + 1) * 3;
        const float* p3 = Xf + (size_t)(f + 2) * 3;
        float u2x = p1[0]-p0[0], u2y = p1[1]-p0[1], u2z = p1[2]-p0[2];
        float u1x = p2[0]-p1[0], u1y = p2[1]-p1[1], u1z = p2[2]-p1[2];
        float u0x = p3[0]-p2[0], u0y = p3[1]-p2[1], u0z = p3[2]-p2[2];
        nrm3(u2x,u2y,u2z); nrm3(u1x,u1y,u1z); nrm3(u0x,u0y,u0z);
        float n2x,n2y,n2z, n1x,n1y,n1z;
        cross3(u2x,u2y,u2z, u1x,u1y,u1z, n2x,n2y,n2z); nrm3(n2x,n2y,n2z);
        cross3(u1x,u1y,u1z, u0x,u0y,u0z, n1x,n1y,n1z); nrm3(n1x,n1y,n1z);
        float cD = n2x*n1x + n2y*n1y + n2z*n1z;
        cD = fminf(fmaxf(cD, -1.0f + 1e-7f), 1.0f - 1e-7f);
        float sg = u2x*n1x + u2y*n1y + u2z*n1z;
        float s  = (sg > 0.0f) ? 1.0f : ((sg < 0.0f) ? -1.0f : 0.0f);
        float D  = s * acosf(cD);
        cosv[t] = cosf(D);
        sinv[t] = sinf(D);
    }

    float4 xc = g_xca[idx];
    float* ns = out + NS_OFF + (size_t)idx * 7;
    ns[0] = cosv[0]; ns[1] = cosv[1]; ns[2] = cosv[2];
    ns[3] = sinv[0]; ns[4] = sinv[1]; ns[5] = sinv[2];
    ns[6] = (__float_as_int(xc.w) & 1) ? 1.0f : 0.0f;

    float fx = 0.f, fy = 0.f, fz = 0.f, bx = 0.f, by = 0.f, bz = 0.f;
    if (n < NN - 1) {
        float4 xn = g_xca[idx + 1];
        fx = xn.x - xc.x; fy = xn.y - xc.y; fz = xn.z - xc.z;
        nrm3(fx, fy, fz);
    }
    if (n > 0) {
        float4 xp = g_xca[idx - 1];
        bx = xp.x - xc.x; by = xp.y - xc.y; bz = xp.z - xc.z;
        nrm3(bx, by, bz);
    }

    const float* at = coords + (size_t)idx * 9;
    float ox = at[3], oy = at[4], oz = at[5];
    float nx = at[0]-ox, ny = at[1]-oy, nz = at[2]-oz;
    float cx = at[6]-ox, cy = at[7]-oy, cz = at[8]-oz;
    nrm3(cx,cy,cz); nrm3(nx,ny,nz);
    float bix = cx+nx, biy = cy+ny, biz = cz+nz; nrm3(bix,biy,biz);
    float px,py,pz; cross3(cx,cy,cz, nx,ny,nz, px,py,pz); nrm3(px,py,pz);
    const float S13 = 0.5773502691896258f;   // sqrt(1/3)
    const float S23 = 0.8164965809277260f;   // sqrt(2/3)
    float sx = -bix*S13 - px*S23;
    float sy = -biy*S13 - py*S23;
    float sz = -biz*S13 - pz*S23;

    float* nv = out + NV_OFF + (size_t)idx * 9;
    nv[0]=fx; nv[1]=fy; nv[2]=fz;
    nv[3]=bx; nv[4]=by; nv[5]=bz;
    nv[6]=sx; nv[7]=sy; nv[8]=sz;
}

// ---------------------------------------------------------------------------
// Top-k, TWO rows per block. Radix-select in the squared-distance domain:
// dadj2 = (cm2 && dr>3) ? s : 0 (+penalties), s = dx^2+dy^2+dz^2+1e-8.
// sqrt is IEEE-monotone, penalties (>=1e8) dwarf real s, so a dadj2-bin
// candidate set is downward-closed under the true dadj order. Exact dadj
// keys (sqrtf on candidates only) feed the O(C^2) rank, which reproduces
// jax.lax.top_k order (ascending value, ties by lowest index) exactly.
// 1024 bins on bits[30:21]; rotated bin -> ((bin&3)<<8)|(bin>>2) so the
// superbin pass (thread tid sums 4 bins at stride 1 KB) is conflict-free.
// Both rows share xj loads, barriers, and the scan schedule; rank phase
// runs warps 0-3 on row0, warps 4-7 on row1.
// ---------------------------------------------------------------------------
__device__ __forceinline__ unsigned long long umin64(unsigned long long a,
                                                     unsigned long long b) {
    return a < b ? a : b;
}

__device__ __forceinline__ void emit(int row, int base, float4 xi, bool cmi,
                                     int rank, int j,
                                     float* __restrict__ out) {
    float4 xj = g_xca[base + j];
    float dx = xj.x - xi.x, dy = xj.y - xi.y, dz = xj.z - xi.z;
    float d  = sqrtf(dx*dx + dy*dy + dz*dz + 1e-8f);
    float D  = (cmi && (__float_as_int(xj.w) & 1)) ? d : 0.0f;
    size_t o = (size_t)row * KK + rank;
    out[DN_OFF + o] = D;
    out[EI_OFF + o] = (float)j;
    out[CM_OFF + o] = (D < 50000000.0f)   ? 1.0f : 0.0f;
    out[RM_OFF + o] = (D < 5000000000.0f) ? 1.0f : 0.0f;
}

__global__ void __launch_bounds__(256) topk_kernel(float* __restrict__ out) {
    __shared__ unsigned int       hist[2][1024];   // 8 KB, rotated layout
    __shared__ unsigned long long cand[2][CAP];    // 4.5 KB
    __shared__ unsigned int       wtot[2][8];
    __shared__ unsigned long long s_win;
    __shared__ int s_cnt[2], s_sb[2], s_excl[2], s_piv[2], s_histpiv[2];

    int row0 = blockIdx.x << 1;
    int b    = row0 >> 11;
    int base = b << 11;
    int i0   = row0 & (NN - 1);
    int i1   = i0 + 1;
    int tid  = threadIdx.x;
    int lane = tid & 31, wid = tid >> 5;

    float4 xi0 = g_xca[row0];
    float4 xi1 = g_xca[row0 + 1];
    int  w0 = __float_as_int(xi0.w), w1 = __float_as_int(xi1.w);
    int  ri0 = w0 >> 2,  ri1 = w1 >> 2;
    bool rm0 = (w0 & 2),  rm1 = (w1 & 2);
    bool cm0 = (w0 & 1),  cm1 = (w1 & 1);

    // ---- phase 1: dadj^2 bits for 8 j's x 2 rows, registers only ----
    unsigned bj0[8], bj1[8];
    #pragma unroll
    for (int q = 0; q < 8; q++) {
        int j = tid + q * 256;
        float4 xj = g_xca[base + j];
        int  wj  = __float_as_int(xj.w);
        int  rj  = wj >> 2;
        bool cmj = (wj & 1), rmj = (wj & 2);
        {   // row 0
            float dx = xj.x - xi0.x, dy = xj.y - xi0.y, dz = xj.z - xi0.z;
            float s  = dx*dx + dy*dy + dz*dz + 1e-8f;
            bool cm2 = cm0 && cmj;
            int  dr  = ri0 - rj; if (dr < 0) dr = -dr;
            float dadj = (cm2 && dr > 3) ? s : 0.0f;
            if (!cm2) {
                int ds = i0 - j; if (ds < 0) ds = -ds;
                dadj += 100000000.0f + (float)ds * 1000000.0f;
            }
            if (!(rm0 && rmj)) dadj += 10000000000.0f;
            bj0[q] = __float_as_uint(dadj);
        }
        {   // row 1
            float dx = xj.x - xi1.x, dy = xj.y - xi1.y, dz = xj.z - xi1.z;
            float s  = dx*dx + dy*dy + dz*dz + 1e-8f;
            bool cm2 = cm1 && cmj;
            int  dr  = ri1 - rj; if (dr < 0) dr = -dr;
            float dadj = (cm2 && dr > 3) ? s : 0.0f;
            if (!cm2) {
                int ds = i1 - j; if (ds < 0) ds = -ds;
                dadj += 100000000.0f + (float)ds * 1000000.0f;
            }
            if (!(rm1 && rmj)) dadj += 10000000000.0f;
            bj1[q] = __float_as_uint(dadj);
        }
    }

    // ---- radix refinement, both rows under one barrier schedule ----
    unsigned fmask[2] = {0, 0}, prefix[2] = {0, 0};
    int shiftv[2] = {21, 21}, kbelow[2] = {0, 0};
    bool active[2] = {true, true}, fellback[2] = {false, false};
    if (tid == 0) { s_cnt[0] = 0; s_cnt[1] = 0; }

    while (active[0] || active[1]) {
        ((uint4*)hist)[tid]       = make_uint4(0u, 0u, 0u, 0u);
        ((uint4*)hist)[tid + 256] = make_uint4(0u, 0u, 0u, 0u);
        __syncthreads();

        if (active[0]) {
            #pragma unroll
            for (int q = 0; q < 8; q++) {
                unsigned bq = bj0[q];
                if ((bq & fmask[0]) == prefix[0]) {
                    unsigned d = (bq >> shiftv[0]) & 1023u;
                    atomicAdd(&hist[0][((d & 3u) << 8) | (d >> 2)], 1u);
                }
            }
        }
        if (active[1]) {
            #pragma unroll
            for (int q = 0; q < 8; q++) {
                unsigned bq = bj1[q];
                if ((bq & fmask[1]) == prefix[1]) {
                    unsigned d = (bq >> shiftv[1]) & 1023u;
                    atomicAdd(&hist[1][((d & 3u) << 8) | (d >> 2)], 1u);
                }
            }
        }
        __syncthreads();

        // superbin sums (4 bins each, conflict-free) + block scan, both rows
        unsigned v0 = 0, v1 = 0;
        #pragma unroll
        for (int q = 0; q < 4; q++) {
            v0 += hist[0][(q << 8) | tid];
            v1 += hist[1][(q << 8) | tid];
        }
        unsigned sc0 = v0, sc1 = v1;
        #pragma unroll
        for (int o = 1; o < 32; o <<= 1) {
            unsigned n0 = __shfl_up_sync(0xffffffffu, sc0, o);
            unsigned n1 = __shfl_up_sync(0xffffffffu, sc1, o);
            if (lane >= o) { sc0 += n0; sc1 += n1; }
        }
        if (lane == 31) { wtot[0][wid] = sc0; wtot[1][wid] = sc1; }
        __syncthreads();
        if (wid == 0) {
            unsigned a0 = (lane < 8) ? wtot[0][lane] : 0;
            unsigned a1 = (lane < 8) ? wtot[1][lane] : 0;
            #pragma unroll
            for (int o = 1; o < 8; o <<= 1) {
                unsigned n0 = __shfl_up_sync(0xffffffffu, a0, o);
                unsigned n1 = __shfl_up_sync(0xffffffffu, a1, o);
                if (lane >= o) { a0 += n0; a1 += n1; }
            }
            if (lane < 8) { wtot[0][lane] = a0; wtot[1][lane] = a1; }
        }
        __syncthreads();

        int kneed0 = KK - kbelow[0], kneed1 = KK - kbelow[1];
        {
            unsigned incl = sc0 + (wid ? wtot[0][wid - 1] : 0);
            unsigned excl = incl - v0;
            if (active[0] && (int)incl >= kneed0 && (int)excl < kneed0) {
                s_sb[0] = tid; s_excl[0] = (int)excl;
            }
            incl = sc1 + (wid ? wtot[1][wid - 1] : 0);
            excl = incl - v1;
            if (active[1] && (int)incl >= kneed1 && (int)excl < kneed1) {
                s_sb[1] = tid; s_excl[1] = (int)excl;
            }
        }
        __syncthreads();
        if (tid < 2) {
            int r = tid;
            if (active[r]) {
                int sb = s_sb[r];
                int kneed = KK - kbelow[r];
                unsigned cum = (unsigned)s_excl[r];
                int pd = sb * 4 + 3; unsigned hp = hist[r][(3u << 8) | sb];
                #pragma unroll
                for (int q = 0; q < 4; q++) {
                    unsigned h = hist[r][(q << 8) | sb];
                    if (cum + h >= (unsigned)kneed) { pd = sb * 4 + q; hp = h; break; }
                    cum += h;
                }
                s_piv[r] = pd; s_excl[r] = (int)cum; s_histpiv[r] = (int)hp;
            }
        }
        __syncthreads();

        #pragma unroll
        for (int r = 0; r < 2; r++) {
            if (!active[r]) continue;
            int below_total = kbelow[r] + s_excl[r];
            unsigned nfmask  = fmask[r] | (1023u << shiftv[r]);
            unsigned nprefix = prefix[r] | ((unsigned)s_piv[r] << shiftv[r]);
            if (below_total + s_histpiv[r] <= CAP) {
                // compact with EXACT keys (sqrt on candidates only)
                #pragma unroll
                for (int q = 0; q < 8; q++) {
                    unsigned bq = (r == 0) ? bj0[q] : bj1[q];
                    if ((bq & nfmask) <= nprefix) {
                        int pos = atomicAdd(&s_cnt[r], 1);
                        if (pos < CAP) {
                            float f = __uint_as_float(bq);
                            unsigned be = (f < 1e8f) ? __float_as_uint(sqrtf(f)) : bq;
                            cand[r][pos] = ((unsigned long long)be << 32)
                                         | (unsigned)(tid + q * 256);
                        }
                    }
                }
                active[r] = false;
            } else if (shiftv[r] == 0) {
                fellback[r] = true; active[r] = false;
            } else {
                fmask[r] = nfmask; prefix[r] = nprefix;
                shiftv[r] = (shiftv[r] >= 11) ? shiftv[r] - 10 : 0;
                kbelow[r] = below_total;
            }
        }
        __syncthreads();
    }

    // ---- rank phase: warps 0-3 -> row0, warps 4-7 -> row1 ----
    {
        int r   = tid >> 7;
        int t0  = tid & 127;
        if (!fellback[r]) {
            int C = s_cnt[r]; if (C > CAP) C = CAP;
            float4 xr = r ? xi1 : xi0;
            bool   cr = r ? cm1 : cm0;
            for (int t = t0; t < C; t += 128) {
                unsigned long long k = cand[r][t];
                int rank = 0;
                for (int c = 0; c < C; c++) rank += (cand[r][c] < k);
                if (rank < KK)
                    emit(row0 + r, base, xr, cr, rank,
                         (int)(unsigned)(k & 0xffffffffu), out);
            }
        }
    }

    // ---- fallback (unreachable for this data): exact min-extraction ----
    #pragma unroll
    for (int r = 0; r < 2; r++) {
        if (!fellback[r]) continue;
        __syncthreads();
        float4 xr = r ? xi1 : xi0;
        bool   cr = r ? cm1 : cm0;
        unsigned taken = 0;
        for (int s = 0; s < KK; s++) {
            unsigned long long local = ~0ULL;
            #pragma unroll
            for (int q = 0; q < 8; q++) {
                unsigned bq = (r == 0) ? bj0[q] : bj1[q];
                float f = __uint_as_float(bq);
                unsigned be = (f < 1e8f) ? __float_as_uint(sqrtf(f)) : bq;
                unsigned long long k = ((unsigned long long)be << 32)
                                     | (unsigned)(tid + q * 256);
                if (!(taken & (1u << q))) local = umin64(local, k);
            }
            #pragma unroll
            for (int o = 16; o > 0; o >>= 1)
                local = umin64(local, __shfl_down_sync(0xffffffffu, local, o));
            if (lane == 0) ((unsigned long long*)hist)[wid] = local;
            __syncthreads();
            if (tid == 0) {
                unsigned long long m = ((unsigned long long*)hist)[0];
                #pragma unroll
                for (int w = 1; w < 8; w++)
                    m = umin64(m, ((unsigned long long*)hist)[w]);
                s_win = m;
                emit(row0 + r, base, xr, cr, s,
                     (int)(unsigned)(m & 0xffffffffu), out);
            }
            __syncthreads();
            unsigned long long m = s_win;
            int j = (int)(unsigned)(m & 0xffffffffu);
            if ((j & 255) == tid) taken |= 1u << (j >> 8);
            __syncthreads();
        }
    }
}

extern "C" void kernel_launch(void* const* d_in, const int* in_sizes, int n_in,
                              void* d_out, int out_size) {
    const float* coords = (const float*)d_in[0];
    const void*  cm     = d_in[1];
    const int*   ridx   = (const int*)d_in[2];
    const void*  pm     = d_in[3];
    float* out = (float*)d_out;

    pack_kernel<<<(BN + 255) / 256, 256>>>(coords, cm, ridx, pm);
    features_kernel<<<(BN + 255) / 256, 256>>>(coords, out);
    topk_kernel<<<BN / 2, 256>>>(out);
}